// round 2
// baseline (speedup 1.0000x reference)
#include <cuda_runtime.h>
#include <math.h>

// Problem constants
#define EMBED 1024
#define NHEAD 16
#define HD    64
#define BATCH 4
#define SEQ   2048

// Scratch: Q/K/V in [sel][b][h][t][d] layout, fp32.
// 3 * 4 * 16 * 2048 * 64 floats = 100.7 MB (static __device__ array: allowed).
__device__ float g_qkv[(size_t)3 * BATCH * NHEAD * SEQ * HD];

// ---------------------------------------------------------------------------
// Kernel 1: QKV projection.  qkv[m, n] = sum_k x[m,k] * W[n,k] + b[n]
// M = B*T = 8192, N = 3*C = 3072, K = C = 1024.  Both A and B are K-major
// row-major, so this is A * B^T with coalesced K-axis loads for both.
// Output written directly into [sel][b][h][t][d] layout; Q pre-scaled by
// 1/sqrt(hd) = 0.125 (fold the softmax scale into the projection).
// ---------------------------------------------------------------------------
__global__ __launch_bounds__(256, 2)
void qkv_gemm_kernel(const float* __restrict__ x,
                     const float* __restrict__ W,
                     const float* __restrict__ bias)
{
    constexpr int BM = 128, BN = 128, BK = 16;
    __shared__ float As[BK][BM + 4];   // [k][m], stride 132 (16B-aligned rows)
    __shared__ float Bs[BK][BN + 4];   // [k][n]

    const int tid = threadIdx.x;            // 256 threads
    const int bm  = blockIdx.y * BM;
    const int bn  = blockIdx.x * BN;

    // global-load mapping: 64 rows x 16 k per pass, 2 passes
    const int lr = tid >> 2;                // 0..63
    const int lc = (tid & 3) << 2;          // 0,4,8,12

    // compute mapping: 16x16 thread grid, 8x8 microtile
    const int ty = tid >> 4;                // 0..15
    const int tx = tid & 15;                // 0..15

    float acc[8][8];
#pragma unroll
    for (int i = 0; i < 8; ++i)
#pragma unroll
        for (int j = 0; j < 8; ++j) acc[i][j] = 0.f;

    const float* xA = x + (size_t)(bm + lr) * EMBED + lc;
    const float* wB = W + (size_t)(bn + lr) * EMBED + lc;

    for (int k0 = 0; k0 < EMBED; k0 += BK) {
#pragma unroll
        for (int h = 0; h < 2; ++h) {
            float4 a = *(const float4*)(xA + (size_t)h * 64 * EMBED + k0);
            As[lc + 0][lr + h * 64] = a.x;
            As[lc + 1][lr + h * 64] = a.y;
            As[lc + 2][lr + h * 64] = a.z;
            As[lc + 3][lr + h * 64] = a.w;
            float4 b = *(const float4*)(wB + (size_t)h * 64 * EMBED + k0);
            Bs[lc + 0][lr + h * 64] = b.x;
            Bs[lc + 1][lr + h * 64] = b.y;
            Bs[lc + 2][lr + h * 64] = b.z;
            Bs[lc + 3][lr + h * 64] = b.w;
        }
        __syncthreads();

#pragma unroll
        for (int k = 0; k < BK; ++k) {
            float a[8], b[8];
            *(float4*)&a[0] = *(const float4*)&As[k][ty * 8];
            *(float4*)&a[4] = *(const float4*)&As[k][ty * 8 + 4];
            *(float4*)&b[0] = *(const float4*)&Bs[k][tx * 4];
            *(float4*)&b[4] = *(const float4*)&Bs[k][64 + tx * 4];
#pragma unroll
            for (int i = 0; i < 8; ++i)
#pragma unroll
                for (int j = 0; j < 8; ++j)
                    acc[i][j] += a[i] * b[j];
        }
        __syncthreads();
    }

    // Epilogue: bias, Q-scale, scatter to [sel][b][h][t][d]
#pragma unroll
    for (int jg = 0; jg < 2; ++jg) {
        const int n4  = bn + jg * 64 + tx * 4;   // 4-aligned, never crosses a head
        const int sel = n4 >> 10;                // 0=Q, 1=K, 2=V
        const int nn  = n4 & 1023;
        const int hh  = nn >> 6;
        const int dd  = nn & 63;
        const float scale = (sel == 0) ? 0.125f : 1.0f;
        float4 bv = *(const float4*)(bias + n4);
#pragma unroll
        for (int i = 0; i < 8; ++i) {
            const int m = bm + ty * 8 + i;
            const int b = m >> 11;               // m / SEQ
            const int t = m & (SEQ - 1);
            float4 v;
            v.x = (acc[i][jg * 4 + 0] + bv.x) * scale;
            v.y = (acc[i][jg * 4 + 1] + bv.y) * scale;
            v.z = (acc[i][jg * 4 + 2] + bv.z) * scale;
            v.w = (acc[i][jg * 4 + 3] + bv.w) * scale;
            const size_t off =
                ((((size_t)sel * BATCH + b) * NHEAD + hh) * SEQ + t) * HD + dd;
            *(float4*)(g_qkv + off) = v;
        }
    }
}

// ---------------------------------------------------------------------------
// Kernel 2: causal flash attention, fp32.
// Grid: (T/64, B*H).  Block: 256 threads.  Each block: 64 query rows,
// iterates K/V in 32-row tiles up to the causal boundary.
// Thread (r = tid/4, g = tid%4): 4 threads per query row.
//   - score phase: thread owns columns c = g + 4j (j<8)   -> conflict-free Ks
//   - output phase: thread owns dims   d = 16jj + 4g (jj<4) -> conflict-free Vs,
//     coalesced y stores.
// Row max/sum reduced across the quad with __shfl_xor (lanes g, g^1, g^2).
// ---------------------------------------------------------------------------
__global__ __launch_bounds__(256, 2)
void attn_kernel(float* __restrict__ y)
{
    __shared__ float Qs[64][68];   // pad 68: rows 4 banks apart, 16B-aligned
    __shared__ float Ks[32][68];
    __shared__ float Vs[32][68];
    __shared__ float Ps[64][36];   // scalar access only; pad 36 ≡ 4 mod 32

    const int tid = threadIdx.x;
    const int qb  = blockIdx.x;          // 0..31 query block
    const int bh  = blockIdx.y;          // 0..63 (b*16 + h)
    const int r   = tid >> 2;            // query row in block, 0..63
    const int g   = tid & 3;             // quad lane

    const float* Qg = g_qkv + ((size_t)bh * SEQ + qb * 64) * HD;     // sel 0
    const float* Kg = g_qkv + ((size_t)(64 + bh) * SEQ) * HD;        // sel 1
    const float* Vg = g_qkv + ((size_t)(128 + bh) * SEQ) * HD;       // sel 2

    // Load Q tile (64 x 64)
    {
        const int row = tid >> 4;                 // 0..15
        const int col = (tid & 15) << 2;          // 0..60
#pragma unroll
        for (int rr = 0; rr < 4; ++rr) {
            float4 v = *(const float4*)(Qg + (size_t)(row + rr * 16) * HD + col);
            *(float4*)&Qs[row + rr * 16][col] = v;
        }
    }

    const float NEG = -1e30f;
    float m = NEG, l = 0.f;
    float4 o[4];
#pragma unroll
    for (int jj = 0; jj < 4; ++jj) o[jj] = make_float4(0.f, 0.f, 0.f, 0.f);

    const int qrow   = qb * 64 + r;
    const int ntiles = 2 * qb + 2;
    const int kr = tid >> 3;             // 0..31 (K/V load row)
    const int kc = (tid & 7) << 3;       // 0..56

    for (int kt = 0; kt < ntiles; ++kt) {
        // Load K,V tiles (32 x 64 each)
        {
            const float* kp = Kg + (size_t)(kt * 32 + kr) * HD + kc;
            const float* vp = Vg + (size_t)(kt * 32 + kr) * HD + kc;
            *(float4*)&Ks[kr][kc]     = *(const float4*)(kp);
            *(float4*)&Ks[kr][kc + 4] = *(const float4*)(kp + 4);
            *(float4*)&Vs[kr][kc]     = *(const float4*)(vp);
            *(float4*)&Vs[kr][kc + 4] = *(const float4*)(vp + 4);
        }
        __syncthreads();

        // --- Phase A: scores s[j] = Q[r,:] . K[g+4j,:]  (Q pre-scaled) ---
        float s[8];
#pragma unroll
        for (int j = 0; j < 8; ++j) s[j] = 0.f;
#pragma unroll
        for (int d0 = 0; d0 < HD; d0 += 4) {
            const float4 q4 = *(const float4*)&Qs[r][d0];
#pragma unroll
            for (int j = 0; j < 8; ++j) {
                const float4 k4 = *(const float4*)&Ks[g + 4 * j][d0];
                s[j] += q4.x * k4.x + q4.y * k4.y + q4.z * k4.z + q4.w * k4.w;
            }
        }

        // Causal mask only needed on the last two tiles of each q-block
        if (kt >= 2 * qb) {
#pragma unroll
            for (int j = 0; j < 8; ++j) {
                const int c = kt * 32 + g + 4 * j;
                if (c > qrow) s[j] = NEG;
            }
        }

        // Online softmax (quad reduction)
        float mx = s[0];
#pragma unroll
        for (int j = 1; j < 8; ++j) mx = fmaxf(mx, s[j]);
        mx = fmaxf(mx, __shfl_xor_sync(0xffffffffu, mx, 1));
        mx = fmaxf(mx, __shfl_xor_sync(0xffffffffu, mx, 2));
        const float m_new = fmaxf(m, mx);
        const float corr  = __expf(m - m_new);     // 0 on first tile
        float sum = 0.f;
#pragma unroll
        for (int j = 0; j < 8; ++j) {
            const float p = __expf(s[j] - m_new);  // underflows to 0 when masked
            Ps[r][g + 4 * j] = p;
            sum += p;
        }
        sum += __shfl_xor_sync(0xffffffffu, sum, 1);
        sum += __shfl_xor_sync(0xffffffffu, sum, 2);
        l = l * corr + sum;
        m = m_new;
#pragma unroll
        for (int jj = 0; jj < 4; ++jj) {
            o[jj].x *= corr; o[jj].y *= corr; o[jj].z *= corr; o[jj].w *= corr;
        }
        __syncthreads();   // Ps visible, phase A done with Ks

        // --- Phase B: O[r, 16jj+4g .. +3] += sum_c P[r,c] * V[c, d] ---
#pragma unroll 4
        for (int c = 0; c < 32; ++c) {
            const float p = Ps[r][c];
#pragma unroll
            for (int jj = 0; jj < 4; ++jj) {
                const float4 v4 = *(const float4*)&Vs[c][jj * 16 + g * 4];
                o[jj].x += p * v4.x; o[jj].y += p * v4.y;
                o[jj].z += p * v4.z; o[jj].w += p * v4.w;
            }
        }
        __syncthreads();   // done with Ps/Vs before next tile overwrites
    }

    // Normalize and store y[b, t, h*64 + d]
    const float inv = 1.0f / l;
    const int b = bh >> 4;
    const int h = bh & 15;
    float* yp = y + ((size_t)b * SEQ + qb * 64 + r) * EMBED + h * HD;
#pragma unroll
    for (int jj = 0; jj < 4; ++jj) {
        float4 v;
        v.x = o[jj].x * inv; v.y = o[jj].y * inv;
        v.z = o[jj].z * inv; v.w = o[jj].w * inv;
        *(float4*)(yp + jj * 16 + g * 4) = v;
    }
}

// ---------------------------------------------------------------------------
extern "C" void kernel_launch(void* const* d_in, const int* in_sizes, int n_in,
                              void* d_out, int out_size)
{
    const float* x    = (const float*)d_in[0];   // [4, 2048, 1024]
    const float* W    = (const float*)d_in[1];   // [3072, 1024]
    const float* bias = (const float*)d_in[2];   // [3072]
    float* y = (float*)d_out;                    // [4, 2048, 1024]

    dim3 gemm_grid(3072 / 128, 8192 / 128);      // (24, 64)
    qkv_gemm_kernel<<<gemm_grid, 256>>>(x, W, bias);

    dim3 attn_grid(SEQ / 64, BATCH * NHEAD);     // (32, 64)
    attn_kernel<<<attn_grid, 256>>>(y);
}

// round 9
// speedup vs baseline: 2.2223x; 2.2223x over previous
#include <cuda_runtime.h>
#include <cuda_bf16.h>
#include <math.h>
#include <stdint.h>

#define EMBED 1024
#define NHEAD 16
#define HD    64
#define BATCH 4
#define SEQ   2048

__device__ float g_qkv[(size_t)3 * BATCH * NHEAD * SEQ * HD];
__device__ __align__(256) __nv_bfloat16 g_xhi[(size_t)BATCH * SEQ * EMBED];
__device__ __align__(256) __nv_bfloat16 g_xlo[(size_t)BATCH * SEQ * EMBED];
__device__ __align__(256) __nv_bfloat16 g_whi[(size_t)3 * EMBED * EMBED];
__device__ __align__(256) __nv_bfloat16 g_wlo[(size_t)3 * EMBED * EMBED];

// ---------------- helpers ----------------
__device__ __forceinline__ uint32_t smem_u32(const void* p) {
    uint32_t a;
    asm("{ .reg .u64 t; cvta.to.shared.u64 t, %1; cvt.u32.u64 %0, t; }" : "=r"(a) : "l"(p));
    return a;
}
__device__ __forceinline__ void cpasync16(uint32_t sa, const void* g) {
    asm volatile("cp.async.cg.shared.global [%0], [%1], 16;" :: "r"(sa), "l"(g));
}
__device__ __forceinline__ void mma16816(float* d, const uint32_t* a, const uint32_t* b) {
    asm volatile(
        "mma.sync.aligned.m16n8k16.row.col.f32.bf16.bf16.f32 "
        "{%0,%1,%2,%3}, {%4,%5,%6,%7}, {%8,%9}, {%0,%1,%2,%3};"
        : "+f"(d[0]), "+f"(d[1]), "+f"(d[2]), "+f"(d[3])
        : "r"(a[0]), "r"(a[1]), "r"(a[2]), "r"(a[3]), "r"(b[0]), "r"(b[1]));
}

// ---------------- split fp32 -> bf16 hi/lo ----------------
__device__ __forceinline__ void split4(float4 v, __nv_bfloat16* hi, __nv_bfloat16* lo, int i) {
    __nv_bfloat16 h0 = __float2bfloat16(v.x), h1 = __float2bfloat16(v.y);
    __nv_bfloat16 h2 = __float2bfloat16(v.z), h3 = __float2bfloat16(v.w);
    ((__nv_bfloat162*)hi)[2*i]   = __halves2bfloat162(h0, h1);
    ((__nv_bfloat162*)hi)[2*i+1] = __halves2bfloat162(h2, h3);
    ((__nv_bfloat162*)lo)[2*i]   = __halves2bfloat162(__float2bfloat16(v.x - __bfloat162float(h0)),
                                                      __float2bfloat16(v.y - __bfloat162float(h1)));
    ((__nv_bfloat162*)lo)[2*i+1] = __halves2bfloat162(__float2bfloat16(v.z - __bfloat162float(h2)),
                                                      __float2bfloat16(v.w - __bfloat162float(h3)));
}
__global__ void split_x_kernel(const float* __restrict__ s) {
    const int n4 = BATCH * SEQ * EMBED / 4;
    for (int i = blockIdx.x * blockDim.x + threadIdx.x; i < n4; i += gridDim.x * blockDim.x)
        split4(((const float4*)s)[i], g_xhi, g_xlo, i);
}
__global__ void split_w_kernel(const float* __restrict__ s) {
    const int n4 = 3 * EMBED * EMBED / 4;
    for (int i = blockIdx.x * blockDim.x + threadIdx.x; i < n4; i += gridDim.x * blockDim.x)
        split4(((const float4*)s)[i], g_whi, g_wlo, i);
}

// ---------------- Kernel 1: QKV GEMM via mma.sync bf16 (split-fp32) --------
// CTA 128x128, 512 thr, warp grid 4x4 (32x32 warp tiles), BK=32, 2-stage
// cp.async pipeline.  D += Ahi*Bhi + Ahi*Blo + Alo*Bhi  (fp32 accum).
// smem rows stride 40 bf16 (80 B = 20 banks): fragment LDS.32 conflict-free.
#define AST 40
#define TILE (128 * AST)              // bf16 per tile
#define BUFB (4 * TILE * 2)           // bytes per stage buffer (40960)
#define GEMM_SMEM (2 * BUFB)          // 81920

__global__ __launch_bounds__(512, 1)
void qkv_gemm_mma(const float* __restrict__ bias)
{
    extern __shared__ __nv_bfloat16 sb[];
    const uint32_t sbase = smem_u32(sb);
    const int tid = threadIdx.x, lane = tid & 31, wid = tid >> 5;
    const int bm = blockIdx.y * 128, bn = blockIdx.x * 128;
    const int wm = (wid >> 2) * 32, wn = (wid & 3) * 32;
    const int frow = lane >> 2, fcol = (lane & 3) * 2;
    const int ldrow = tid >> 2, ldchunk = tid & 3;   // stage fill: 128 rows x 4 chunks

    float acc[2][4][4];
#pragma unroll
    for (int im = 0; im < 2; ++im)
#pragma unroll
        for (int in = 0; in < 4; ++in)
#pragma unroll
            for (int r = 0; r < 4; ++r) acc[im][in][r] = 0.f;

    // prologue: stage 0 -> buf 0
#pragma unroll
    for (int t = 0; t < 4; ++t) {
        const __nv_bfloat16* src = (t == 0) ? g_xhi : (t == 1) ? g_xlo : (t == 2) ? g_whi : g_wlo;
        const int rb = (t < 2) ? bm : bn;
        cpasync16(sbase + t * (TILE * 2) + ldrow * (AST * 2) + ldchunk * 16,
                  src + (size_t)(rb + ldrow) * EMBED + ldchunk * 8);
    }
    asm volatile("cp.async.commit_group;");

    const int NS = EMBED / 32;   // 32 stages
    for (int s = 0; s < NS; ++s) {
        const int buf = s & 1;
        if (s + 1 < NS) {
            const int k0 = (s + 1) * 32;
            const uint32_t dst = sbase + (buf ^ 1) * BUFB;
#pragma unroll
            for (int t = 0; t < 4; ++t) {
                const __nv_bfloat16* src = (t == 0) ? g_xhi : (t == 1) ? g_xlo : (t == 2) ? g_whi : g_wlo;
                const int rb = (t < 2) ? bm : bn;
                cpasync16(dst + t * (TILE * 2) + ldrow * (AST * 2) + ldchunk * 16,
                          src + (size_t)(rb + ldrow) * EMBED + k0 + ldchunk * 8);
            }
            asm volatile("cp.async.commit_group;");
            asm volatile("cp.async.wait_group 1;");
        } else {
            asm volatile("cp.async.wait_group 0;");
        }
        __syncthreads();

        const __nv_bfloat16* bp = sb + buf * (4 * TILE);
        const __nv_bfloat16* Ah = bp;
        const __nv_bfloat16* Al = bp + TILE;
        const __nv_bfloat16* Bh = bp + 2 * TILE;
        const __nv_bfloat16* Bl = bp + 3 * TILE;
#pragma unroll
        for (int ks = 0; ks < 2; ++ks) {
            const int kb = ks * 16;
            uint32_t ah[2][4], al[2][4], bh[4][2], bl[4][2];
#pragma unroll
            for (int im = 0; im < 2; ++im) {
                const int base = (wm + im * 16 + frow) * AST + kb + fcol;
                ah[im][0] = *(const uint32_t*)(Ah + base);
                ah[im][1] = *(const uint32_t*)(Ah + base + 8 * AST);
                ah[im][2] = *(const uint32_t*)(Ah + base + 8);
                ah[im][3] = *(const uint32_t*)(Ah + base + 8 * AST + 8);
                al[im][0] = *(const uint32_t*)(Al + base);
                al[im][1] = *(const uint32_t*)(Al + base + 8 * AST);
                al[im][2] = *(const uint32_t*)(Al + base + 8);
                al[im][3] = *(const uint32_t*)(Al + base + 8 * AST + 8);
            }
#pragma unroll
            for (int in = 0; in < 4; ++in) {
                const int nb = (wn + in * 8 + frow) * AST + kb + fcol;
                bh[in][0] = *(const uint32_t*)(Bh + nb);
                bh[in][1] = *(const uint32_t*)(Bh + nb + 8);
                bl[in][0] = *(const uint32_t*)(Bl + nb);
                bl[in][1] = *(const uint32_t*)(Bl + nb + 8);
            }
#pragma unroll
            for (int im = 0; im < 2; ++im)
#pragma unroll
                for (int in = 0; in < 4; ++in) {
                    mma16816(acc[im][in], ah[im], bh[in]);
                    mma16816(acc[im][in], ah[im], bl[in]);
                    mma16816(acc[im][in], al[im], bh[in]);
                }
        }
        __syncthreads();
    }

    // Epilogue: bias + Q-scale, scatter to g_qkv[sel][b][h][t][d].
#pragma unroll
    for (int im = 0; im < 2; ++im) {
#pragma unroll
        for (int in = 0; in < 4; ++in) {
            const int n0 = bn + wn + in * 8 + fcol;
            const int sel = n0 >> 10, hh = (n0 >> 6) & 15, dd = n0 & 63;
            const float sc = (sel == 0) ? 0.125f : 1.0f;
            const float b0 = __ldg(bias + n0), b1 = __ldg(bias + n0 + 1);
#pragma unroll
            for (int half = 0; half < 2; ++half) {
                const int mg = bm + wm + im * 16 + frow + half * 8;
                const int bb = mg >> 11, tt = mg & (SEQ - 1);
                float2 v;
                v.x = (acc[im][in][half * 2 + 0] + b0) * sc;
                v.y = (acc[im][in][half * 2 + 1] + b1) * sc;
                *(float2*)(g_qkv +
                    ((((size_t)sel * BATCH + bb) * NHEAD + hh) * SEQ + tt) * HD + dd) = v;
            }
        }
    }
}

// ---------------- Kernel 2: flash attention, 4x8 register microtile ----------
#define ATTN_SMEM ((128 * 68 + 2 * 64 * 68 + 128 * 68) * 4)

__global__ __launch_bounds__(256, 2)
void attn_kernel(float* __restrict__ y)
{
    extern __shared__ float sm[];
    float* Qs = sm;                         // [128][68]
    float* Ks = sm + 128 * 68;              // [64][68]
    float* Vs = Ks + 64 * 68;               // [64][68]
    float* Ps = Vs + 64 * 68;               // [128][68]

    const int tid = threadIdx.x;
    const int qb = 15 - blockIdx.y;         // heavy blocks first
    const int bh = blockIdx.x;
    const int tx = tid & 7, ty = tid >> 3;  // ty 0..31

    const float* Qg = g_qkv + ((size_t)bh * SEQ + qb * 128) * HD;
    const float* Kg = g_qkv + ((size_t)(64 + bh) * SEQ) * HD;
    const float* Vg = g_qkv + ((size_t)(128 + bh) * SEQ) * HD;

    for (int idx = tid; idx < 128 * 16; idx += 256) {
        const int row = idx >> 4, c4 = (idx & 15) * 4;
        *(float4*)&Qs[row * 68 + c4] = *(const float4*)(Qg + (size_t)row * HD + c4);
    }

    float m[4], l[4], o[4][8];
#pragma unroll
    for (int i = 0; i < 4; ++i) {
        m[i] = -1e30f; l[i] = 0.f;
#pragma unroll
        for (int d = 0; d < 8; ++d) o[i][d] = 0.f;
    }

    const int ntiles = 2 * qb + 2;
    for (int kt = 0; kt < ntiles; ++kt) {
        __syncthreads();
        for (int idx = tid; idx < 64 * 16; idx += 256) {
            const int row = idx >> 4, c4 = (idx & 15) * 4;
            *(float4*)&Ks[row * 68 + c4] = *(const float4*)(Kg + (size_t)(kt * 64 + row) * HD + c4);
            *(float4*)&Vs[row * 68 + c4] = *(const float4*)(Vg + (size_t)(kt * 64 + row) * HD + c4);
        }
        __syncthreads();

        // Phase A: S = Q K^T (Q pre-scaled by 0.125 in GEMM epilogue)
        float s[4][8];
#pragma unroll
        for (int i = 0; i < 4; ++i)
#pragma unroll
            for (int j = 0; j < 8; ++j) s[i][j] = 0.f;
#pragma unroll 4
        for (int d0 = 0; d0 < HD; d0 += 4) {
            float4 q[4];
#pragma unroll
            for (int i = 0; i < 4; ++i) q[i] = *(const float4*)&Qs[(ty + 32 * i) * 68 + d0];
#pragma unroll
            for (int j = 0; j < 8; ++j) {
                const float4 kv = *(const float4*)&Ks[(tx + 8 * j) * 68 + d0];
#pragma unroll
                for (int i = 0; i < 4; ++i)
                    s[i][j] += q[i].x * kv.x + q[i].y * kv.y + q[i].z * kv.z + q[i].w * kv.w;
            }
        }
        if (kt >= 2 * qb) {  // causal mask on final two tiles only
#pragma unroll
            for (int i = 0; i < 4; ++i) {
                const int qrow = qb * 128 + ty + 32 * i;
#pragma unroll
                for (int j = 0; j < 8; ++j)
                    if (kt * 64 + tx + 8 * j > qrow) s[i][j] = -1e30f;
            }
        }
        // Online softmax; reduce across the 8 tx lanes
#pragma unroll
        for (int i = 0; i < 4; ++i) {
            float mx = s[i][0];
#pragma unroll
            for (int j = 1; j < 8; ++j) mx = fmaxf(mx, s[i][j]);
            mx = fmaxf(mx, __shfl_xor_sync(0xffffffffu, mx, 1));
            mx = fmaxf(mx, __shfl_xor_sync(0xffffffffu, mx, 2));
            mx = fmaxf(mx, __shfl_xor_sync(0xffffffffu, mx, 4));
            const float mn = fmaxf(m[i], mx);
            const float corr = __expf(m[i] - mn);
            float sum = 0.f;
#pragma unroll
            for (int j = 0; j < 8; ++j) {
                const float p = __expf(s[i][j] - mn);
                Ps[(ty + 32 * i) * 68 + tx + 8 * j] = p;
                sum += p;
            }
            sum += __shfl_xor_sync(0xffffffffu, sum, 1);
            sum += __shfl_xor_sync(0xffffffffu, sum, 2);
            sum += __shfl_xor_sync(0xffffffffu, sum, 4);
            l[i] = l[i] * corr + sum;
            m[i] = mn;
#pragma unroll
            for (int d = 0; d < 8; ++d) o[i][d] *= corr;
        }
        __syncthreads();

        // Phase B: O[r, {tx*4+d, 32+tx*4+d}] += sum_c P[r,c] * V[c, .]
#pragma unroll 2
        for (int c = 0; c < 64; ++c) {
            const float4 v0 = *(const float4*)&Vs[c * 68 + tx * 4];
            const float4 v1 = *(const float4*)&Vs[c * 68 + 32 + tx * 4];
#pragma unroll
            for (int i = 0; i < 4; ++i) {
                const float p = Ps[(ty + 32 * i) * 68 + c];
                o[i][0] += p * v0.x; o[i][1] += p * v0.y;
                o[i][2] += p * v0.z; o[i][3] += p * v0.w;
                o[i][4] += p * v1.x; o[i][5] += p * v1.y;
                o[i][6] += p * v1.z; o[i][7] += p * v1.w;
            }
        }
    }

    const int b = bh >> 4, h = bh & 15;
#pragma unroll
    for (int i = 0; i < 4; ++i) {
        const float inv = 1.0f / l[i];
        float* yp = y + ((size_t)b * SEQ + qb * 128 + ty + 32 * i) * EMBED + h * HD;
        float4 a, c;
        a.x = o[i][0] * inv; a.y = o[i][1] * inv; a.z = o[i][2] * inv; a.w = o[i][3] * inv;
        c.x = o[i][4] * inv; c.y = o[i][5] * inv; c.z = o[i][6] * inv; c.w = o[i][7] * inv;
        *(float4*)(yp + tx * 4) = a;
        *(float4*)(yp + 32 + tx * 4) = c;
    }
}

// ---------------------------------------------------------------------------
extern "C" void kernel_launch(void* const* d_in, const int* in_sizes, int n_in,
                              void* d_out, int out_size)
{
    const float* x = (const float*)d_in[0];
    const float* W = (const float*)d_in[1];
    const float* bias = (const float*)d_in[2];
    float* y = (float*)d_out;

    cudaFuncSetAttribute(qkv_gemm_mma, cudaFuncAttributeMaxDynamicSharedMemorySize, GEMM_SMEM);
    cudaFuncSetAttribute(attn_kernel, cudaFuncAttributeMaxDynamicSharedMemorySize, ATTN_SMEM);

    split_x_kernel<<<512, 256>>>(x);
    split_w_kernel<<<256, 256>>>(W);

    dim3 gg(3072 / 128, 8192 / 128);      // (24, 64)
    qkv_gemm_mma<<<gg, 512, GEMM_SMEM>>>(bias);

    dim3 ag(BATCH * NHEAD, SEQ / 128);    // (64, 16)
    attn_kernel<<<ag, 256, ATTN_SMEM>>>(y);
}